// round 14
// baseline (speedup 1.0000x reference)
#include <cuda_runtime.h>
#include <cuda_bf16.h>
#include <cstdint>

#define NB 256
#define IN_F 1024
#define B_EXTRA 256
#define KDIM 16
#define OUT_F 1280
#define JDIM 4096            // B_EXTRA * KDIM

// ---------------- device scratch ----------------
__device__ float g_M[NB * JDIM];                       // 4 MB
__device__ __nv_bfloat16 g_xb[NB * IN_F];              // 512 KB [m][k]
__device__ __nv_bfloat16 g_Wb[(size_t)IN_F * JDIM];    // 8 MB  [k][n]

// ---------------- helpers ----------------
__device__ __forceinline__ uint32_t smem_u32(const void* p) {
    uint32_t a;
    asm("{ .reg .u64 t; cvta.to.shared.u64 t, %1; cvt.u32.u64 %0, t; }" : "=r"(a) : "l"(p));
    return a;
}
#define SWZ(x) ((x) ^ (((x) >> 3) & 0x70))

__device__ __forceinline__ void cp16(uint32_t dst, const void* src) {
    asm volatile("cp.async.cg.shared.global [%0], [%1], 16;" :: "r"(dst), "l"(src) : "memory");
}
#define CP_COMMIT() asm volatile("cp.async.commit_group;" ::: "memory")
#define CP_WAITG1() asm volatile("cp.async.wait_group 1;" ::: "memory")
#define CP_WAITG0() asm volatile("cp.async.wait_group 0;" ::: "memory")

__device__ __forceinline__ void ldsm_x4(uint32_t* r, uint32_t a) {
    asm volatile("ldmatrix.sync.aligned.m8n8.x4.shared.b16 {%0,%1,%2,%3}, [%4];"
        : "=r"(r[0]), "=r"(r[1]), "=r"(r[2]), "=r"(r[3]) : "r"(a));
}
__device__ __forceinline__ void ldsm_x4_t(uint32_t* r, uint32_t a) {
    asm volatile("ldmatrix.sync.aligned.m8n8.x4.trans.shared.b16 {%0,%1,%2,%3}, [%4];"
        : "=r"(r[0]), "=r"(r[1]), "=r"(r[2]), "=r"(r[3]) : "r"(a));
}
__device__ __forceinline__ void mma_16816(float* d, const uint32_t* a, const uint32_t* b) {
    asm volatile("mma.sync.aligned.m16n8k16.row.col.f32.bf16.bf16.f32 "
        "{%0,%1,%2,%3}, {%4,%5,%6,%7}, {%8,%9}, {%0,%1,%2,%3};"
        : "+f"(d[0]), "+f"(d[1]), "+f"(d[2]), "+f"(d[3])
        : "r"(a[0]), "r"(a[1]), "r"(a[2]), "r"(a[3]), "r"(b[0]), "r"(b[1]));
}
__device__ __forceinline__ uint32_t cvt_bf16x2(float flo, float fhi) {
    uint32_t d;
    asm("cvt.rn.bf16x2.f32 %0, %1, %2;" : "=r"(d) : "f"(fhi), "f"(flo));
    return d;
}
__device__ __forceinline__ int vad4add(uint32_t a, uint32_t b, int c) {
    int d;
    asm("vabsdiff4.u32.s32.s32.add %0, %1, %2, %3;" : "=r"(d) : "r"(a), "r"(b), "r"(c));
    return d;
}
__device__ __forceinline__ float ex2f(float v) {
    float y;
    asm("ex2.approx.f32 %0, %1;" : "=f"(y) : "f"(v));
    return y;
}

// ---------------------------------------------------------------------------
// Kernel 1: prep (champion) — W -> bf16 (blocks < 2048); x -> bf16 + x-copy.
// ---------------------------------------------------------------------------
__global__ __launch_bounds__(256) void prep_kernel(const float* __restrict__ x,
                                                   const float* __restrict__ W,
                                                   float* __restrict__ out) {
    const int blk = blockIdx.x;
    const int tid = threadIdx.x;
    if (blk < 2048) {
        const size_t i = ((size_t)blk * 256 + tid) * 8;
        float4 u = *(const float4*)(W + i);
        float4 v = *(const float4*)(W + i + 4);
        uint4 o;
        o.x = cvt_bf16x2(u.x, u.y); o.y = cvt_bf16x2(u.z, u.w);
        o.z = cvt_bf16x2(v.x, v.y); o.w = cvt_bf16x2(v.z, v.w);
        *(uint4*)(g_Wb + i) = o;
    } else {
        const int j = (blk - 2048) * 256 + tid;
        {
            const size_t i = (size_t)j * 8;
            float4 u = *(const float4*)(x + i);
            float4 v = *(const float4*)(x + i + 4);
            uint4 o;
            o.x = cvt_bf16x2(u.x, u.y); o.y = cvt_bf16x2(u.z, u.w);
            o.z = cvt_bf16x2(v.x, v.y); o.w = cvt_bf16x2(v.z, v.w);
            *(uint4*)(g_xb + i) = o;
        }
#pragma unroll
        for (int p = 0; p < 2; p++) {
            const int g = j + p * 32768;
            const int row = g >> 8;
            const int c = g & 255;
            ((float4*)(out + (size_t)row * OUT_F))[c] =
                ((const float4*)(x + (size_t)row * IN_F))[c];
        }
    }
}

// ---------------------------------------------------------------------------
// Kernel 2: bf16 HMMA GEMM (champion): 3-stage cp.async, CTA 128x64, BK=64.
// ---------------------------------------------------------------------------
#define BM 128
#define BN 64
#define BK 64
#define NT_K 16
#define STG_SZ 24576
#define SA(s) ((s) * STG_SZ)
#define SB(s) ((s) * STG_SZ + 16384)
#define GEMM_SMEM (3 * STG_SZ)

__global__ __launch_bounds__(256) void gemm_kernel() {
    extern __shared__ __align__(1024) char smem[];
    const uint32_t sbase = smem_u32(smem);
    const int tid = threadIdx.x;
    const int wid = tid >> 5;
    const int lane = tid & 31;
    const int m0 = blockIdx.y * BM;
    const int n0 = blockIdx.x * BN;
    const int wm = (wid >> 1) * 32;
    const int wn = (wid & 1) * 32;
    const int c8 = tid & 7;

    auto issue_tile = [&](int t) {
        const int s = t % 3;
        const int kk = t * BK;
        const uint32_t Ab = sbase + SA(s);
        const uint32_t Bb = sbase + SB(s);
#pragma unroll
        for (int q = 0; q < 4; q++) {
            const int r = (tid + q * 256) >> 3;
            cp16(Ab + SWZ(r * 128 + c8 * 16),
                 g_xb + (size_t)(m0 + r) * IN_F + kk + c8 * 8);
        }
#pragma unroll
        for (int q = 0; q < 2; q++) {
            const int r = (tid + q * 256) >> 3;
            cp16(Bb + SWZ(r * 128 + c8 * 16),
                 g_Wb + (size_t)(kk + r) * JDIM + n0 + c8 * 8);
        }
        CP_COMMIT();
    };

    float acc[2][4][4] = {};

    issue_tile(0);
    issue_tile(1);

    for (int t = 0; t < NT_K; t++) {
        if (t + 2 < NT_K) CP_WAITG1(); else CP_WAITG0();
        __syncthreads();
        if (t + 2 < NT_K) issue_tile(t + 2);

        const int s = t % 3;
        const uint32_t Ab = sbase + SA(s);
        const uint32_t Bb = sbase + SB(s);
#pragma unroll
        for (int st = 0; st < 4; st++) {
            uint32_t af[2][4], bf[2][4];
#pragma unroll
            for (int mt = 0; mt < 2; mt++)
                ldsm_x4(af[mt], Ab + SWZ((wm + mt * 16 + (lane & 15)) * 128 +
                                         st * 32 + (lane >> 4) * 16));
#pragma unroll
            for (int nt = 0; nt < 2; nt++)
                ldsm_x4_t(bf[nt], Bb + SWZ((st * 16 + (lane & 15)) * 128 +
                                           (wn + nt * 16) * 2 + (lane >> 4) * 16));
#pragma unroll
            for (int mt = 0; mt < 2; mt++)
#pragma unroll
                for (int j = 0; j < 4; j++)
                    mma_16816(acc[mt][j], af[mt], bf[j >> 1] + (j & 1) * 2);
        }
        __syncthreads();
    }

    const int g = lane >> 2, tig = lane & 3;
#pragma unroll
    for (int mt = 0; mt < 2; mt++)
#pragma unroll
        for (int j = 0; j < 4; j++) {
            const size_t base = (size_t)(m0 + wm + mt * 16 + g) * JDIM +
                                n0 + wn + j * 8 + tig * 2;
            *(float2*)(g_M + base)            = make_float2(acc[mt][j][0], acc[mt][j][1]);
            *(float2*)(g_M + base + 8 * JDIM) = make_float2(acc[mt][j][2], acc[mt][j][3]);
        }
}

// ---------------------------------------------------------------------------
// Kernel 3: pairwise L1 + exp-sum via int8 SAD, 2 m-rows per thread.
// Grid = 256 blocks (one per b) x 512 threads:
//   p = tid & 127 -> handles m0 = p and m1 = p + 128
//   quart = tid >> 7 -> n range [quart*64, quart*64 + 64)
// Each sQ[n] load is shared by both m-rows (halves LDS traffic).
// Partials in sP[256][4]; exact -1 self-term preserved.
// ---------------------------------------------------------------------------
__global__ __launch_bounds__(512) void pairwise_kernel(float* __restrict__ out) {
    __shared__ __align__(16) uint4 sQ[NB];    // 4 KB quantized rows
    __shared__ float sWmax[8];
    __shared__ float sP[NB][4];               // 4 KB partials
    const int b = blockIdx.x;
    const int tid = threadIdx.x;
    const int lane = tid & 31;
    const int wid = tid >> 5;

    // threads < 256: load own M row, block max, quantize, publish
    if (tid < 256) {
        const float* rowp = g_M + (size_t)tid * JDIM + b * KDIM;
        float f[16];
#pragma unroll
        for (int q = 0; q < 4; q++) {
            float4 v = ((const float4*)rowp)[q];
            f[4 * q] = v.x; f[4 * q + 1] = v.y; f[4 * q + 2] = v.z; f[4 * q + 3] = v.w;
        }
        float mx = fabsf(f[0]);
#pragma unroll
        for (int k = 1; k < 16; k++) mx = fmaxf(mx, fabsf(f[k]));
#pragma unroll
        for (int o = 16; o; o >>= 1) mx = fmaxf(mx, __shfl_xor_sync(0xFFFFFFFFu, mx, o));
        if (lane == 0) sWmax[wid] = mx;
        __syncthreads();   // barrier 1
        float bm = sWmax[0];
#pragma unroll
        for (int w = 1; w < 8; w++) bm = fmaxf(bm, sWmax[w]);
        bm = fmaxf(bm, 1e-20f);
        const float s = 127.0f / bm;
        uint32_t q32[4];
#pragma unroll
        for (int q = 0; q < 4; q++) {
            const int a0 = __float2int_rn(f[4 * q] * s);
            const int a1 = __float2int_rn(f[4 * q + 1] * s);
            const int a2 = __float2int_rn(f[4 * q + 2] * s);
            const int a3 = __float2int_rn(f[4 * q + 3] * s);
            q32[q] = (a0 & 255) | ((a1 & 255) << 8) | ((a2 & 255) << 16) | (a3 << 24);
        }
        sQ[tid] = make_uint4(q32[0], q32[1], q32[2], q32[3]);
    } else {
        __syncthreads();   // barrier 1 (match)
    }
    __syncthreads();       // barrier 2: sQ published

    float bm = sWmax[0];
#pragma unroll
    for (int w = 1; w < 8; w++) bm = fmaxf(bm, sWmax[w]);
    bm = fmaxf(bm, 1e-20f);
    const float negc = -bm * (1.44269504088896f / 127.0f);
    const float offs = -8388608.0f * negc;   // cancels the 2^23 magic bias

    const int p = tid & 127;
    const int quart = tid >> 7;              // 0..3
    const uint4 mqA = sQ[p];                 // m0 = p
    const uint4 mqB = sQ[p + 128];           // m1 = p + 128

    float accA0 = 0.0f, accA1 = 0.0f, accB0 = 0.0f, accB1 = 0.0f;
    const int nb = quart * 64;
#pragma unroll 4
    for (int i = 0; i < 32; i++) {
        const int n = nb + 2 * i;
        const uint4 qa = sQ[n];
        const uint4 qb = sQ[n + 1];
        // m0 vs n, n+1
        int sA0 = vad4add(qa.x, mqA.x, 0);
        int sA1 = vad4add(qb.x, mqA.x, 0);
        // m1 vs n, n+1
        int sB0 = vad4add(qa.x, mqB.x, 0);
        int sB1 = vad4add(qb.x, mqB.x, 0);
        sA0 = vad4add(qa.y, mqA.y, sA0);
        sA1 = vad4add(qb.y, mqA.y, sA1);
        sB0 = vad4add(qa.y, mqB.y, sB0);
        sB1 = vad4add(qb.y, mqB.y, sB1);
        sA0 = vad4add(qa.z, mqA.z, sA0);
        sA1 = vad4add(qb.z, mqA.z, sA1);
        sB0 = vad4add(qa.z, mqB.z, sB0);
        sB1 = vad4add(qb.z, mqB.z, sB1);
        sA0 = vad4add(qa.w, mqA.w, sA0);
        sA1 = vad4add(qb.w, mqA.w, sA1);
        sB0 = vad4add(qa.w, mqB.w, sB0);
        sB1 = vad4add(qb.w, mqB.w, sB1);
        // magic int->float: asfloat(0x4B000000|s) = 2^23 + s (exact, s < 2^23)
        const float fA0 = __uint_as_float(0x4B000000u | (uint32_t)sA0);
        const float fA1 = __uint_as_float(0x4B000000u | (uint32_t)sA1);
        const float fB0 = __uint_as_float(0x4B000000u | (uint32_t)sB0);
        const float fB1 = __uint_as_float(0x4B000000u | (uint32_t)sB1);
        accA0 += ex2f(fmaf(fA0, negc, offs));
        accA1 += ex2f(fmaf(fA1, negc, offs));
        accB0 += ex2f(fmaf(fB0, negc, offs));
        accB1 += ex2f(fmaf(fB1, negc, offs));
    }
    sP[p][quart]       = accA0 + accA1;
    sP[p + 128][quart] = accB0 + accB1;
    __syncthreads();       // barrier 3

    if (tid < 256)
        out[(size_t)tid * OUT_F + IN_F + b] =
            ((sP[tid][0] + sP[tid][1]) + (sP[tid][2] + sP[tid][3])) - 1.0f;
}

extern "C" void kernel_launch(void* const* d_in, const int* in_sizes, int n_in,
                              void* d_out, int out_size) {
    const float* x = (const float*)d_in[0];   // (256, 1024)
    const float* T = (const float*)d_in[1];   // (1024, 256, 16) == W[k][n]
    float* out = (float*)d_out;               // (256, 1280)

    prep_kernel<<<2176, 256>>>(x, T, out);

    cudaFuncSetAttribute(gemm_kernel, cudaFuncAttributeMaxDynamicSharedMemorySize, GEMM_SMEM);
    gemm_kernel<<<dim3(JDIM / BN, NB / BM), 256, GEMM_SMEM>>>();

    pairwise_kernel<<<B_EXTRA, 512>>>(out);
}

// round 15
// speedup vs baseline: 1.0969x; 1.0969x over previous
#include <cuda_runtime.h>
#include <cuda_bf16.h>
#include <cstdint>

#define NB 256
#define IN_F 1024
#define B_EXTRA 256
#define KDIM 16
#define OUT_F 1280
#define JDIM 4096            // B_EXTRA * KDIM

// ---------------- device scratch ----------------
__device__ float g_M[NB * JDIM];                       // 4 MB
__device__ __nv_bfloat16 g_xb[NB * IN_F];              // 512 KB [m][k]
__device__ __nv_bfloat16 g_Wb[(size_t)IN_F * JDIM];    // 8 MB  [k][n]

// ---------------- helpers ----------------
__device__ __forceinline__ uint32_t smem_u32(const void* p) {
    uint32_t a;
    asm("{ .reg .u64 t; cvta.to.shared.u64 t, %1; cvt.u32.u64 %0, t; }" : "=r"(a) : "l"(p));
    return a;
}
#define SWZ(x) ((x) ^ (((x) >> 3) & 0x70))

__device__ __forceinline__ void cp16(uint32_t dst, const void* src) {
    asm volatile("cp.async.cg.shared.global [%0], [%1], 16;" :: "r"(dst), "l"(src) : "memory");
}
#define CP_COMMIT() asm volatile("cp.async.commit_group;" ::: "memory")
#define CP_WAITG1() asm volatile("cp.async.wait_group 1;" ::: "memory")
#define CP_WAITG0() asm volatile("cp.async.wait_group 0;" ::: "memory")

__device__ __forceinline__ void ldsm_x4(uint32_t* r, uint32_t a) {
    asm volatile("ldmatrix.sync.aligned.m8n8.x4.shared.b16 {%0,%1,%2,%3}, [%4];"
        : "=r"(r[0]), "=r"(r[1]), "=r"(r[2]), "=r"(r[3]) : "r"(a));
}
__device__ __forceinline__ void ldsm_x4_t(uint32_t* r, uint32_t a) {
    asm volatile("ldmatrix.sync.aligned.m8n8.x4.trans.shared.b16 {%0,%1,%2,%3}, [%4];"
        : "=r"(r[0]), "=r"(r[1]), "=r"(r[2]), "=r"(r[3]) : "r"(a));
}
__device__ __forceinline__ void mma_16816(float* d, const uint32_t* a, const uint32_t* b) {
    asm volatile("mma.sync.aligned.m16n8k16.row.col.f32.bf16.bf16.f32 "
        "{%0,%1,%2,%3}, {%4,%5,%6,%7}, {%8,%9}, {%0,%1,%2,%3};"
        : "+f"(d[0]), "+f"(d[1]), "+f"(d[2]), "+f"(d[3])
        : "r"(a[0]), "r"(a[1]), "r"(a[2]), "r"(a[3]), "r"(b[0]), "r"(b[1]));
}
__device__ __forceinline__ uint32_t cvt_bf16x2(float flo, float fhi) {
    uint32_t d;
    asm("cvt.rn.bf16x2.f32 %0, %1, %2;" : "=r"(d) : "f"(fhi), "f"(flo));
    return d;
}
__device__ __forceinline__ int vad4add(uint32_t a, uint32_t b, int c) {
    int d;
    asm("vabsdiff4.u32.s32.s32.add %0, %1, %2, %3;" : "=r"(d) : "r"(a), "r"(b), "r"(c));
    return d;
}

// Schraudolph/Mitchell 2^x bias: (127<<23) - 362570 (minimax-centered, ±3.0%)
#define EXP_BIAS 1064990646

// ---------------------------------------------------------------------------
// Kernel 1: prep (champion) — W -> bf16 (blocks < 2048); x -> bf16 + x-copy.
// ---------------------------------------------------------------------------
__global__ __launch_bounds__(256) void prep_kernel(const float* __restrict__ x,
                                                   const float* __restrict__ W,
                                                   float* __restrict__ out) {
    const int blk = blockIdx.x;
    const int tid = threadIdx.x;
    if (blk < 2048) {
        const size_t i = ((size_t)blk * 256 + tid) * 8;
        float4 u = *(const float4*)(W + i);
        float4 v = *(const float4*)(W + i + 4);
        uint4 o;
        o.x = cvt_bf16x2(u.x, u.y); o.y = cvt_bf16x2(u.z, u.w);
        o.z = cvt_bf16x2(v.x, v.y); o.w = cvt_bf16x2(v.z, v.w);
        *(uint4*)(g_Wb + i) = o;
    } else {
        const int j = (blk - 2048) * 256 + tid;
        {
            const size_t i = (size_t)j * 8;
            float4 u = *(const float4*)(x + i);
            float4 v = *(const float4*)(x + i + 4);
            uint4 o;
            o.x = cvt_bf16x2(u.x, u.y); o.y = cvt_bf16x2(u.z, u.w);
            o.z = cvt_bf16x2(v.x, v.y); o.w = cvt_bf16x2(v.z, v.w);
            *(uint4*)(g_xb + i) = o;
        }
#pragma unroll
        for (int p = 0; p < 2; p++) {
            const int g = j + p * 32768;
            const int row = g >> 8;
            const int c = g & 255;
            ((float4*)(out + (size_t)row * OUT_F))[c] =
                ((const float4*)(x + (size_t)row * IN_F))[c];
        }
    }
}

// ---------------------------------------------------------------------------
// Kernel 2: bf16 HMMA GEMM (champion): 3-stage cp.async, CTA 128x64, BK=64.
// ---------------------------------------------------------------------------
#define BM 128
#define BN 64
#define BK 64
#define NT_K 16
#define STG_SZ 24576
#define SA(s) ((s) * STG_SZ)
#define SB(s) ((s) * STG_SZ + 16384)
#define GEMM_SMEM (3 * STG_SZ)

__global__ __launch_bounds__(256) void gemm_kernel() {
    extern __shared__ __align__(1024) char smem[];
    const uint32_t sbase = smem_u32(smem);
    const int tid = threadIdx.x;
    const int wid = tid >> 5;
    const int lane = tid & 31;
    const int m0 = blockIdx.y * BM;
    const int n0 = blockIdx.x * BN;
    const int wm = (wid >> 1) * 32;
    const int wn = (wid & 1) * 32;
    const int c8 = tid & 7;

    auto issue_tile = [&](int t) {
        const int s = t % 3;
        const int kk = t * BK;
        const uint32_t Ab = sbase + SA(s);
        const uint32_t Bb = sbase + SB(s);
#pragma unroll
        for (int q = 0; q < 4; q++) {
            const int r = (tid + q * 256) >> 3;
            cp16(Ab + SWZ(r * 128 + c8 * 16),
                 g_xb + (size_t)(m0 + r) * IN_F + kk + c8 * 8);
        }
#pragma unroll
        for (int q = 0; q < 2; q++) {
            const int r = (tid + q * 256) >> 3;
            cp16(Bb + SWZ(r * 128 + c8 * 16),
                 g_Wb + (size_t)(kk + r) * JDIM + n0 + c8 * 8);
        }
        CP_COMMIT();
    };

    float acc[2][4][4] = {};

    issue_tile(0);
    issue_tile(1);

    for (int t = 0; t < NT_K; t++) {
        if (t + 2 < NT_K) CP_WAITG1(); else CP_WAITG0();
        __syncthreads();
        if (t + 2 < NT_K) issue_tile(t + 2);

        const int s = t % 3;
        const uint32_t Ab = sbase + SA(s);
        const uint32_t Bb = sbase + SB(s);
#pragma unroll
        for (int st = 0; st < 4; st++) {
            uint32_t af[2][4], bf[2][4];
#pragma unroll
            for (int mt = 0; mt < 2; mt++)
                ldsm_x4(af[mt], Ab + SWZ((wm + mt * 16 + (lane & 15)) * 128 +
                                         st * 32 + (lane >> 4) * 16));
#pragma unroll
            for (int nt = 0; nt < 2; nt++)
                ldsm_x4_t(bf[nt], Bb + SWZ((st * 16 + (lane & 15)) * 128 +
                                           (wn + nt * 16) * 2 + (lane >> 4) * 16));
#pragma unroll
            for (int mt = 0; mt < 2; mt++)
#pragma unroll
                for (int j = 0; j < 4; j++)
                    mma_16816(acc[mt][j], af[mt], bf[j >> 1] + (j & 1) * 2);
        }
        __syncthreads();
    }

    const int g = lane >> 2, tig = lane & 3;
#pragma unroll
    for (int mt = 0; mt < 2; mt++)
#pragma unroll
        for (int j = 0; j < 4; j++) {
            const size_t base = (size_t)(m0 + wm + mt * 16 + g) * JDIM +
                                n0 + wn + j * 8 + tig * 2;
            *(float2*)(g_M + base)            = make_float2(acc[mt][j][0], acc[mt][j][1]);
            *(float2*)(g_M + base + 8 * JDIM) = make_float2(acc[mt][j][2], acc[mt][j][3]);
        }
}

// ---------------------------------------------------------------------------
// Kernel 3: pairwise L1 + exp-sum via int8 SAD + Schraudolph integer exp.
//   exp(-l1) ~ asfloat(max(sa*K + BIAS, 0)),  K = round(-bm*log2e/127 * 2^23)
// Self-term (sa==0) evaluates exactly to asfloat(BIAS) -> subtracted exactly.
// Grid = 256 blocks (one per b) x 512 threads = (m = tid&255, half = tid>>8).
// ---------------------------------------------------------------------------
__global__ __launch_bounds__(512) void pairwise_kernel(float* __restrict__ out) {
    __shared__ __align__(16) uint4 sQ[NB];    // 4 KB quantized rows
    __shared__ float sWmax[8];
    __shared__ float sP[NB][2];               // 2 KB partials
    const int b = blockIdx.x;
    const int tid = threadIdx.x;
    const int m = tid & 255;
    const int half = tid >> 8;
    const int lane = tid & 31;
    const int wid = tid >> 5;

    // threads < 256: load own M row, block max, quantize, publish
    if (half == 0) {
        const float* rowp = g_M + (size_t)m * JDIM + b * KDIM;
        float f[16];
#pragma unroll
        for (int q = 0; q < 4; q++) {
            float4 v = ((const float4*)rowp)[q];
            f[4 * q] = v.x; f[4 * q + 1] = v.y; f[4 * q + 2] = v.z; f[4 * q + 3] = v.w;
        }
        float mx = fabsf(f[0]);
#pragma unroll
        for (int k = 1; k < 16; k++) mx = fmaxf(mx, fabsf(f[k]));
#pragma unroll
        for (int o = 16; o; o >>= 1) mx = fmaxf(mx, __shfl_xor_sync(0xFFFFFFFFu, mx, o));
        if (lane == 0) sWmax[wid] = mx;
        __syncthreads();   // barrier 1
        float bm = sWmax[0];
#pragma unroll
        for (int w = 1; w < 8; w++) bm = fmaxf(bm, sWmax[w]);
        bm = fmaxf(bm, 1e-20f);
        const float s = 127.0f / bm;
        uint32_t q32[4];
#pragma unroll
        for (int q = 0; q < 4; q++) {
            const int a0 = __float2int_rn(f[4 * q] * s);
            const int a1 = __float2int_rn(f[4 * q + 1] * s);
            const int a2 = __float2int_rn(f[4 * q + 2] * s);
            const int a3 = __float2int_rn(f[4 * q + 3] * s);
            q32[q] = (a0 & 255) | ((a1 & 255) << 8) | ((a2 & 255) << 16) | (a3 << 24);
        }
        sQ[m] = make_uint4(q32[0], q32[1], q32[2], q32[3]);
    } else {
        __syncthreads();   // barrier 1 (match)
    }
    __syncthreads();       // barrier 2: sQ published

    float bm = sWmax[0];
#pragma unroll
    for (int w = 1; w < 8; w++) bm = fmaxf(bm, sWmax[w]);
    bm = fmaxf(bm, 1e-20f);
    // K = round(-bm * log2(e)/127 * 2^23); |K| <= ~4e5 for bm <= ~4.3
    const int K = __float2int_rn(bm * (-8388608.0f * 1.44269504088896f / 127.0f));

    const uint4 mq = sQ[m];
    const uint32_t myq0 = mq.x, myq1 = mq.y, myq2 = mq.z, myq3 = mq.w;

    float acc0 = 0.0f, acc1 = 0.0f;
    const int nbase = half * 128;
#pragma unroll 4
    for (int i = 0; i < 64; i++) {
        const int n = nbase + 2 * i;
        const uint4 qa = sQ[n];
        const uint4 qb = sQ[n + 1];
        int sa = vad4add(qa.x, myq0, 0);
        int sb = vad4add(qb.x, myq0, 0);
        int sa2 = vad4add(qa.y, myq1, 0);
        int sb2 = vad4add(qb.y, myq1, 0);
        sa = vad4add(qa.z, myq2, sa);
        sb = vad4add(qb.z, myq2, sb);
        sa2 = vad4add(qa.w, myq3, sa2);
        sb2 = vad4add(qb.w, myq3, sb2);
        // 2^((sa)*negc) ~ asfloat(max((sa)*K + BIAS, 0))  [IMAD + IMNMX]
        const int ba = max((sa + sa2) * K + EXP_BIAS, 0);
        const int bb = max((sb + sb2) * K + EXP_BIAS, 0);
        acc0 += __int_as_float(ba);
        acc1 += __int_as_float(bb);
    }
    sP[m][half] = acc0 + acc1;
    __syncthreads();       // barrier 3

    // self term (sa==0) contributed exactly asfloat(EXP_BIAS): subtract it.
    if (half == 0)
        out[(size_t)m * OUT_F + IN_F + b] =
            (sP[m][0] + sP[m][1]) - __int_as_float(EXP_BIAS);
}

extern "C" void kernel_launch(void* const* d_in, const int* in_sizes, int n_in,
                              void* d_out, int out_size) {
    const float* x = (const float*)d_in[0];   // (256, 1024)
    const float* T = (const float*)d_in[1];   // (1024, 256, 16) == W[k][n]
    float* out = (float*)d_out;               // (256, 1280)

    prep_kernel<<<2176, 256>>>(x, T, out);

    cudaFuncSetAttribute(gemm_kernel, cudaFuncAttributeMaxDynamicSharedMemorySize, GEMM_SMEM);
    gemm_kernel<<<dim3(JDIM / BN, NB / BM), 256, GEMM_SMEM>>>();

    pairwise_kernel<<<B_EXTRA, 512>>>(out);
}